// round 5
// baseline (speedup 1.0000x reference)
#include <cuda_runtime.h>

#define NB   128
#define CIN  64
#define TDIM 128
#define VV   25
#define RR   8
#define OO   64
#define TVPOS 3200   // TDIM*VV

typedef unsigned long long u64;

// ---- scratch (device globals: no allocation allowed) ----
__device__ float g_part1[NB*4*RR*VV];        // per (n,split) partial T-sums branch1
__device__ float g_part2[NB*4*RR*VV];        // branch2
__device__ float g_pstat[NB*4*4];            // per (n,split): s1,q1,s2,q2
__device__ float g_ysum[(size_t)NB*OO*VV*VV];// [n][c][u][v]  (20 MB, fits L2)

// ---- packed fp32x2 helpers (FFMA2 only reachable via PTX) ----
__device__ __forceinline__ u64 pk2(float a, float b){
    u64 r; asm("mov.b64 %0,{%1,%2};" : "=l"(r) : "f"(a), "f"(b)); return r;
}
__device__ __forceinline__ void upk2(u64 v, float& a, float& b){
    asm("mov.b64 {%0,%1},%2;" : "=f"(a), "=f"(b) : "l"(v));
}
__device__ __forceinline__ void fma2(u64& d, u64 a, u64 b){
    asm("fma.rn.f32x2 %0,%1,%2,%0;" : "+l"(d) : "l"(a), "l"(b));
}

__device__ __forceinline__ int div25(int p){ return (p*1311) >> 15; }  // valid p<256

extern __shared__ char smem_raw[];

#define XROW 516   // floats per v-row in kA: 64ci*8t + 4 pad; 516%32==4 -> conflict-free
                   // LDS.128 phases; 516*4 bytes is 16B-aligned.

// ============================================================
// Kernel A v3: stats pass. grid (4 splits, 128 n), 256 thr, 3 CTA/SM.
// smem layout xs[v][ci][8t] (row stride XROW) so lane(=v) reads its
// 8 t-values as two LDS.128 and accumulates with packed f32x2 FMA.
// 12 issue slots per ci vs 25 before.
// ============================================================
__global__ void __launch_bounds__(256, 3) kA(const float* __restrict__ x,
        const float* __restrict__ w1, const float* __restrict__ b1,
        const float* __restrict__ w2, const float* __restrict__ b2)
{
    u64*   w1p = (u64*)smem_raw;           // 512 u64
    u64*   w2p = w1p + 512;                // 512 u64
    float* xs  = (float*)(w2p + 512);      // 25*XROW floats
    float* red = xs + 25*XROW;             // 32

    int tid = threadIdx.x;
    int split = blockIdx.x, n = blockIdx.y;
    int w = tid >> 5, lane = tid & 31;

    for (int i = tid; i < 512; i += 256) {
        float a = w1[i]; w1p[i] = pk2(a, a);
        float c = w2[i]; w2p[i] = pk2(c, c);
    }
    float b1r = b1[w], b2r = b2[w];
    float part1 = 0.f, part2 = 0.f, q1 = 0.f, q2 = 0.f;
    const float4* xn4 = (const float4*)(x + (size_t)n*CIN*TVPOS + split*800);
    __syncthreads();

    for (int tile = 0; tile < 4; ++tile) {
        // load 64ci x 200 pos (float4 coalesced), scatter to [v][ci][t]
        for (int i = tid; i < 3200; i += 256) {
            int ci = i / 50, j = i - ci*50;
            float4 v4 = xn4[ci*800 + tile*50 + j];
            int p = 4*j;
            float e[4] = {v4.x, v4.y, v4.z, v4.w};
            #pragma unroll
            for (int k = 0; k < 4; ++k) {
                int pp = p + k;
                int t = div25(pp), v = pp - t*25;
                xs[v*XROW + ci*8 + t] = e[k];
            }
        }
        __syncthreads();
        if (lane < 25) {
            u64 a1[4], a2[4];
            #pragma unroll
            for (int j = 0; j < 4; ++j) { a1[j] = pk2(0.f,0.f); a2[j] = a1[j]; }
            const u64* wr1 = w1p + w*64;
            const u64* wr2 = w2p + w*64;
            const float* xb = xs + lane*XROW;
            #pragma unroll 4
            for (int ci = 0; ci < 64; ++ci) {
                ulonglong2 x01 = *(const ulonglong2*)(xb + ci*8);
                ulonglong2 x23 = *(const ulonglong2*)(xb + ci*8 + 4);
                u64 wa = wr1[ci], wb = wr2[ci];
                fma2(a1[0], wa, x01.x); fma2(a1[1], wa, x01.y);
                fma2(a1[2], wa, x23.x); fma2(a1[3], wa, x23.y);
                fma2(a2[0], wb, x01.x); fma2(a2[1], wb, x01.y);
                fma2(a2[2], wb, x23.x); fma2(a2[3], wb, x23.y);
            }
            #pragma unroll
            for (int j = 0; j < 4; ++j) {
                float f0, f1, g0, g1;
                upk2(a1[j], f0, f1); upk2(a2[j], g0, g1);
                f0 += b1r; f1 += b1r; g0 += b2r; g1 += b2r;
                part1 += f0 + f1;  q1 += f0*f0 + f1*f1;
                part2 += g0 + g1;  q2 += g0*g0 + g1*g1;
            }
        }
        __syncthreads();
    }

    if (lane < 25) {
        g_part1[(n*4 + split)*200 + w*25 + lane] = part1;
        g_part2[(n*4 + split)*200 + w*25 + lane] = part2;
    } else {
        part1 = 0.f; part2 = 0.f; q1 = 0.f; q2 = 0.f;
    }
    float s1 = part1, s2 = part2;
    #pragma unroll
    for (int off = 16; off; off >>= 1) {
        s1 += __shfl_xor_sync(0xffffffffu, s1, off);
        q1 += __shfl_xor_sync(0xffffffffu, q1, off);
        s2 += __shfl_xor_sync(0xffffffffu, s2, off);
        q2 += __shfl_xor_sync(0xffffffffu, q2, off);
    }
    if (lane == 0) { red[w*4+0]=s1; red[w*4+1]=q1; red[w*4+2]=s2; red[w*4+3]=q2; }
    __syncthreads();
    if (tid < 4) {
        float acc = 0.f;
        #pragma unroll
        for (int ww = 0; ww < 8; ++ww) acc += red[ww*4 + tid];
        g_pstat[(n*4 + split)*4 + tid] = acc;
    }
}

// ============================================================
// Kernel B: per-sample finalize.  grid 128, 256 threads.
// GN-affine + mean(T) -> x1,x2 [8][25]; build ysum[n][64][25][25].
// ============================================================
__global__ void __launch_bounds__(256) kB(const float* __restrict__ Aadj,
    const float* __restrict__ g1, const float* __restrict__ be1,
    const float* __restrict__ g2, const float* __restrict__ be2,
    const float* __restrict__ w4, const float* __restrict__ b4)
{
    __shared__ float x1s[200], x2s[200], yss[5000], w4s[512], st[4];
    int n = blockIdx.x, tid = threadIdx.x;

    if (tid < 4) {
        float s = 0.f;
        for (int k = 0; k < 4; ++k) s += g_pstat[(n*4 + k)*4 + tid];
        st[tid] = s;
    }
    for (int i = tid; i < 512; i += 256) w4s[i] = w4[i];
    float sum1 = 0.f, sum2 = 0.f;
    if (tid < 200) {
        for (int k = 0; k < 4; ++k) {
            sum1 += g_part1[(n*4 + k)*200 + tid];
            sum2 += g_part2[(n*4 + k)*200 + tid];
        }
    }
    __syncthreads();
    if (tid < 200) {
        const float inv = 1.0f / 25600.0f;     // R*T*V
        float mu1 = st[0]*inv, var1 = st[1]*inv - mu1*mu1;
        float mu2 = st[2]*inv, var2 = st[3]*inv - mu2*mu2;
        float rs1 = rsqrtf(var1 + 1e-5f), rs2 = rsqrtf(var2 + 1e-5f);
        int r = tid / 25;
        x1s[tid] = (sum1*(1.0f/128.0f) - mu1)*rs1*g1[r] + be1[r];
        x2s[tid] = (sum2*(1.0f/128.0f) - mu2)*rs2*g2[r] + be2[r];
    }
    __syncthreads();
    for (int i = tid; i < 5000; i += 256) {
        int r = i / 625, rem = i - r*625;
        int u = rem / 25, v = rem - u*25;
        yss[i] = tanhf(x1s[r*25+u] - x1s[r*25+v])
               + tanhf(x2s[r*25+u] * x2s[r*25+v])
               + __ldg(Aadj + rem);
    }
    __syncthreads();
    float* dst = g_ysum + (size_t)n*40000;
    for (int i = tid; i < 40000; i += 256) {
        int c = i / 625, p = i - c*625;
        float a = b4[c];
        #pragma unroll
        for (int r = 0; r < 8; ++r) a += w4s[c*8 + r]*yss[r*625 + p];
        dst[i] = a;
    }
}

// ============================================================
// Kernel C v3: like v2 but phase-3 ysum goes through a coalesced
// smem stage (reusing the w3 region, dead after phase 2) instead of
// strided per-lane LDG — kills the L1tex wavefront storm.
// grid (16 t-tiles of 8, 128 n), 256 threads, 2 CTAs/SM, 90KB smem.
// ============================================================
__global__ void __launch_bounds__(256, 2) kC(const float* __restrict__ x,
    const float* __restrict__ w3, const float* __restrict__ b3,
    float* __restrict__ out)
{
    u64*   w3ps = (u64*)smem_raw;          // 4096 u64  [ci][64c]  (32KB)
    float* ysc  = (float*)smem_raw;        // alias: 5000 f stage after phase 2
    float* xbuf = (float*)(w3ps + 4096);   // 64*224 floats (x, then x3 in place)

    int tid = threadIdx.x;
    int tt = blockIdx.x, n = blockIdx.y;
    int w = tid >> 5, lane = tid & 31;

    for (int i = tid; i < 4096; i += 256) {
        int c = i >> 6, ci = i & 63;
        float wv = w3[i];                   // w3[c][ci]
        w3ps[ci*64 + c] = pk2(wv, wv);
    }
    // load x tile: 64ci x 200 pos, scatter into padded [t*28+v] layout
    const float4* xn4 = (const float4*)(x + (size_t)n*CIN*TVPOS + tt*200);
    for (int i = tid; i < 3200; i += 256) {
        int ci = i / 50, j = i - ci*50;
        float4 v4 = xn4[ci*800 + j];
        int p = 4*j;
        float e[4] = {v4.x, v4.y, v4.z, v4.w};
        #pragma unroll
        for (int k = 0; k < 4; ++k) {
            int pp = p + k;
            int t = div25(pp), v = pp - t*25;
            xbuf[ci*224 + t*28 + v] = e[k];
        }
    }
    for (int i = tid; i < 1536; i += 256) {   // zero the 3-wide v pads
        int ci = i / 24, r = i - ci*24;
        int t = r / 3;
        xbuf[ci*224 + t*28 + 25 + (r - t*3)] = 0.0f;
    }
    __syncthreads();

    // ---- phase 2: x3 = W3*x + b3, in place, two disjoint passes ----
    int c0 = w*8;
    #pragma unroll
    for (int pass = 0; pass < 2; ++pass) {
        int q = pass*28 + lane;             // float4 quad index within row
        bool act = (lane < 28);
        u64 acc[8][2];
        if (act) {
            #pragma unroll
            for (int j = 0; j < 8; ++j) {
                float bv = __ldg(b3 + c0 + j);
                acc[j][0] = pk2(bv, bv); acc[j][1] = acc[j][0];
            }
            #pragma unroll 4
            for (int ci = 0; ci < 64; ++ci) {
                ulonglong2 xv = *(const ulonglong2*)(xbuf + ci*224 + 4*q);
                const ulonglong2* wr = (const ulonglong2*)(w3ps + ci*64 + c0);
                ulonglong2 w01 = wr[0], w23 = wr[1], w45 = wr[2], w67 = wr[3];
                fma2(acc[0][0], w01.x, xv.x); fma2(acc[0][1], w01.x, xv.y);
                fma2(acc[1][0], w01.y, xv.x); fma2(acc[1][1], w01.y, xv.y);
                fma2(acc[2][0], w23.x, xv.x); fma2(acc[2][1], w23.x, xv.y);
                fma2(acc[3][0], w23.y, xv.x); fma2(acc[3][1], w23.y, xv.y);
                fma2(acc[4][0], w45.x, xv.x); fma2(acc[4][1], w45.x, xv.y);
                fma2(acc[5][0], w45.y, xv.x); fma2(acc[5][1], w45.y, xv.y);
                fma2(acc[6][0], w67.x, xv.x); fma2(acc[6][1], w67.x, xv.y);
                fma2(acc[7][0], w67.y, xv.x); fma2(acc[7][1], w67.y, xv.y);
            }
        }
        __syncthreads();                    // all reads of this range done
        if (act) {
            #pragma unroll
            for (int j = 0; j < 8; ++j) {
                u64* row = (u64*)(xbuf + (c0 + j)*224);
                row[2*q]     = acc[j][0];
                row[2*q + 1] = acc[j][1];
            }
        }
    }

    // ---- phase 3: out[c,t,u] = sum_v ysum[c,u,v]*x3[c,t,v], f32x2,
    //      ysum staged 8 channels at a time through smem (coalesced) ----
    const float* ysrc = g_ysum + (size_t)n*40000;
    for (int cc = 0; cc < 8; ++cc) {
        __syncthreads();                    // phase-2 stores / prior-stage reads done
        for (int i = tid; i < 1250; i += 256)
            ((float4*)ysc)[i] = ((const float4*)(ysrc + cc*5000))[i];
        __syncthreads();
        if (lane < 25) {
            int c = cc*8 + w;               // global channel
            const float* yr = ysc + w*625 + lane*25;   // u = lane, conflict-free LDS
            u64 yp[13];
            #pragma unroll
            for (int j = 0; j < 12; ++j) yp[j] = pk2(yr[2*j], yr[2*j+1]);
            yp[12] = pk2(yr[24], 0.0f);     // x3 pad holds b3, times 0 -> safe
            u64 acc2[8];
            #pragma unroll
            for (int t = 0; t < 8; ++t) acc2[t] = pk2(0.f, 0.f);
            const u64* xrow = (const u64*)(xbuf + c*224);
            #pragma unroll
            for (int j = 0; j < 13; ++j) {
                #pragma unroll
                for (int t = 0; t < 8; ++t)
                    fma2(acc2[t], yp[j], xrow[t*14 + j]);
            }
            float* od = out + (((size_t)n*64 + c)*128 + tt*8)*25 + lane;
            #pragma unroll
            for (int t = 0; t < 8; ++t) {
                float lo, hi; upk2(acc2[t], lo, hi);
                od[t*25] = lo + hi;
            }
        }
    }
}

// ============================================================
extern "C" void kernel_launch(void* const* d_in, const int* in_sizes, int n_in,
                              void* d_out, int out_size)
{
    (void)in_sizes; (void)n_in; (void)out_size;
    const float* x   = (const float*)d_in[0];
    const float* A   = (const float*)d_in[1];
    const float* w1  = (const float*)d_in[2];
    const float* b1  = (const float*)d_in[3];
    const float* g1  = (const float*)d_in[4];
    const float* be1 = (const float*)d_in[5];
    const float* w2  = (const float*)d_in[6];
    const float* b2  = (const float*)d_in[7];
    const float* g2  = (const float*)d_in[8];
    const float* be2 = (const float*)d_in[9];
    const float* w3  = (const float*)d_in[10];
    const float* b3  = (const float*)d_in[11];
    const float* w4  = (const float*)d_in[12];
    const float* b4  = (const float*)d_in[13];
    float* out = (float*)d_out;

    const int smemA = 512*8*2 + 25*XROW*4 + 32*4;   // 8192+51600+128 = 59920
    const int smemC = 4096*8 + 64*224*4;            // 90112
    cudaFuncSetAttribute(kA, cudaFuncAttributeMaxDynamicSharedMemorySize, smemA);
    cudaFuncSetAttribute(kC, cudaFuncAttributeMaxDynamicSharedMemorySize, smemC);

    kA<<<dim3(4, 128), 256, smemA>>>(x, w1, b1, w2, b2);
    kB<<<128, 256>>>(A, g1, be1, g2, be2, w4, b4);
    kC<<<dim3(16, 128), 256, smemC>>>(x, w3, b3, out);
}

// round 6
// speedup vs baseline: 1.2870x; 1.2870x over previous
#include <cuda_runtime.h>

#define NB   128
#define CIN  64
#define TDIM 128
#define VV   25
#define RR   8
#define OO   64
#define TVPOS 3200   // TDIM*VV
#define YSTR 640     // padded ysum channel stride (16B-aligned float4 staging)

typedef unsigned long long u64;

// ---- scratch (device globals: no allocation allowed) ----
__device__ float g_part1[NB*4*RR*VV];
__device__ float g_part2[NB*4*RR*VV];
__device__ float g_pstat[NB*4*4];
__device__ float g_ysum[(size_t)NB*OO*YSTR];   // [n][c][640], 625 used

// ---- packed fp32x2 helpers (FFMA2 only reachable via PTX) ----
__device__ __forceinline__ u64 pk2(float a, float b){
    u64 r; asm("mov.b64 %0,{%1,%2};" : "=l"(r) : "f"(a), "f"(b)); return r;
}
__device__ __forceinline__ void upk2(u64 v, float& a, float& b){
    asm("mov.b64 {%0,%1},%2;" : "=f"(a), "=f"(b) : "l"(v));
}
__device__ __forceinline__ void fma2(u64& d, u64 a, u64 b){
    asm("fma.rn.f32x2 %0,%1,%2,%0;" : "+l"(d) : "l"(a), "l"(b));
}

__device__ __forceinline__ int div25(int p){ return (p*1311) >> 15; }  // valid p<256

extern __shared__ char smem_raw[];

// ============================================================
// Kernel A (R3 version, known 61us): stats pass, no atomics.
// grid (4 splits, 128 n), 256 thr.  warp->r, lane->v (lane<25).
// xs natural t-major [ci][t*25+v]; scalar LDS conflict-free.
// ============================================================
__global__ void __launch_bounds__(256, 4) kA(const float* __restrict__ x,
        const float* __restrict__ w1, const float* __restrict__ b1,
        const float* __restrict__ w2, const float* __restrict__ b2)
{
    float2* wz = (float2*)smem_raw;        // [8][64] packed (w1,w2)
    float*  xs = (float*)(wz + 512);       // [64][200]
    float*  red = xs + 12800;              // [8][4]

    int tid = threadIdx.x;
    int split = blockIdx.x, n = blockIdx.y;
    int w = tid >> 5, lane = tid & 31;

    for (int i = tid; i < 512; i += 256)
        wz[i] = make_float2(w1[i], w2[i]);

    float b1r = b1[w], b2r = b2[w];
    float part1 = 0.f, part2 = 0.f, q1 = 0.f, q2 = 0.f;
    const float4* xn4 = (const float4*)(x + (size_t)n*CIN*TVPOS + split*800);
    __syncthreads();

    for (int tile = 0; tile < 4; ++tile) {
        for (int i = tid; i < 3200; i += 256) {
            int ci = i / 50, j = i - ci*50;
            ((float4*)xs)[ci*50 + j] = xn4[ci*800 + tile*50 + j];
        }
        __syncthreads();
        if (lane < 25) {
            float p1[8], p2[8];
            #pragma unroll
            for (int t = 0; t < 8; ++t) { p1[t] = 0.f; p2[t] = 0.f; }
            const float2* wr = wz + w*64;
            const float* xb = xs + lane;
            #pragma unroll 4
            for (int ci = 0; ci < 64; ++ci) {
                float2 wv = wr[ci];
                const float* xc = xb + ci*200;
                #pragma unroll
                for (int t = 0; t < 8; ++t) {
                    float xv = xc[t*25];
                    p1[t] += wv.x * xv;
                    p2[t] += wv.y * xv;
                }
            }
            #pragma unroll
            for (int t = 0; t < 8; ++t) {
                float f = p1[t] + b1r, g = p2[t] + b2r;
                part1 += f; q1 += f*f;
                part2 += g; q2 += g*g;
            }
        }
        __syncthreads();
    }

    if (lane < 25) {
        g_part1[(n*4 + split)*200 + w*25 + lane] = part1;
        g_part2[(n*4 + split)*200 + w*25 + lane] = part2;
    } else {
        part1 = 0.f; part2 = 0.f; q1 = 0.f; q2 = 0.f;
    }
    float s1 = part1, s2 = part2;
    #pragma unroll
    for (int off = 16; off; off >>= 1) {
        s1 += __shfl_xor_sync(0xffffffffu, s1, off);
        q1 += __shfl_xor_sync(0xffffffffu, q1, off);
        s2 += __shfl_xor_sync(0xffffffffu, s2, off);
        q2 += __shfl_xor_sync(0xffffffffu, q2, off);
    }
    if (lane == 0) { red[w*4+0]=s1; red[w*4+1]=q1; red[w*4+2]=s2; red[w*4+3]=q2; }
    __syncthreads();
    if (tid < 4) {
        float acc = 0.f;
        #pragma unroll
        for (int ww = 0; ww < 8; ++ww) acc += red[ww*4 + tid];
        g_pstat[(n*4 + split)*4 + tid] = acc;
    }
}

// ============================================================
// Kernel B: per-sample finalize -> ysum (padded stride 640).
// ============================================================
__global__ void __launch_bounds__(256) kB(const float* __restrict__ Aadj,
    const float* __restrict__ g1, const float* __restrict__ be1,
    const float* __restrict__ g2, const float* __restrict__ be2,
    const float* __restrict__ w4, const float* __restrict__ b4)
{
    __shared__ float x1s[200], x2s[200], yss[5000], w4s[512], st[4];
    int n = blockIdx.x, tid = threadIdx.x;

    if (tid < 4) {
        float s = 0.f;
        for (int k = 0; k < 4; ++k) s += g_pstat[(n*4 + k)*4 + tid];
        st[tid] = s;
    }
    for (int i = tid; i < 512; i += 256) w4s[i] = w4[i];
    float sum1 = 0.f, sum2 = 0.f;
    if (tid < 200) {
        for (int k = 0; k < 4; ++k) {
            sum1 += g_part1[(n*4 + k)*200 + tid];
            sum2 += g_part2[(n*4 + k)*200 + tid];
        }
    }
    __syncthreads();
    if (tid < 200) {
        const float inv = 1.0f / 25600.0f;     // R*T*V
        float mu1 = st[0]*inv, var1 = st[1]*inv - mu1*mu1;
        float mu2 = st[2]*inv, var2 = st[3]*inv - mu2*mu2;
        float rs1 = rsqrtf(var1 + 1e-5f), rs2 = rsqrtf(var2 + 1e-5f);
        int r = tid / 25;
        x1s[tid] = (sum1*(1.0f/128.0f) - mu1)*rs1*g1[r] + be1[r];
        x2s[tid] = (sum2*(1.0f/128.0f) - mu2)*rs2*g2[r] + be2[r];
    }
    __syncthreads();
    for (int i = tid; i < 5000; i += 256) {
        int r = i / 625, rem = i - r*625;
        int u = rem / 25, v = rem - u*25;
        yss[i] = tanhf(x1s[r*25+u] - x1s[r*25+v])
               + tanhf(x2s[r*25+u] * x2s[r*25+v])
               + __ldg(Aadj + rem);
    }
    __syncthreads();
    float* dst = g_ysum + (size_t)n*OO*YSTR;
    for (int i = tid; i < 40000; i += 256) {
        int c = i / 625, p = i - c*625;
        float a = b4[c];
        #pragma unroll
        for (int r = 0; r < 8; ++r) a += w4s[c*8 + r]*yss[r*625 + p];
        dst[c*YSTR + p] = a;
    }
}

// ============================================================
// Kernel C v4: phase 1+2 as R3 (in-place FFMA2 GEMM); phase 3
// uses WARP-PRIVATE ysum staging: warp w copies channel (cc*8+w)'s
// 640-float row-block into its own smem slice (coalesced float4),
// __syncwarp only — zero CTA barriers, ~12x fewer L1tex wavefronts
// than the strided per-lane LDG pattern.
// grid (16 t-tiles of 8, 128 n), 256 threads, 2 CTAs/SM, 90KB smem.
// ============================================================
__global__ void __launch_bounds__(256, 2) kC(const float* __restrict__ x,
    const float* __restrict__ w3, const float* __restrict__ b3,
    float* __restrict__ out)
{
    u64*   w3ps = (u64*)smem_raw;          // 4096 u64  [ci][64c]  (32KB)
    float* ybuf = (float*)smem_raw;        // alias after phase 2: [8 warps][640]
    float* xbuf = (float*)(w3ps + 4096);   // 64*224 floats (x, then x3 in place)

    int tid = threadIdx.x;
    int tt = blockIdx.x, n = blockIdx.y;
    int w = tid >> 5, lane = tid & 31;

    for (int i = tid; i < 4096; i += 256) {
        int c = i >> 6, ci = i & 63;
        float wv = w3[i];                   // w3[c][ci]
        w3ps[ci*64 + c] = pk2(wv, wv);
    }
    // load x tile: 64ci x 200 pos, scatter into padded [t*28+v] layout
    const float4* xn4 = (const float4*)(x + (size_t)n*CIN*TVPOS + tt*200);
    for (int i = tid; i < 3200; i += 256) {
        int ci = i / 50, j = i - ci*50;
        float4 v4 = xn4[ci*800 + j];
        int p = 4*j;
        float e[4] = {v4.x, v4.y, v4.z, v4.w};
        #pragma unroll
        for (int k = 0; k < 4; ++k) {
            int pp = p + k;
            int t = div25(pp), v = pp - t*25;
            xbuf[ci*224 + t*28 + v] = e[k];
        }
    }
    for (int i = tid; i < 1536; i += 256) {   // zero the 3-wide v pads
        int ci = i / 24, r = i - ci*24;
        int t = r / 3;
        xbuf[ci*224 + t*28 + 25 + (r - t*3)] = 0.0f;
    }
    __syncthreads();

    // ---- phase 2: x3 = W3*x + b3, in place, two disjoint passes ----
    int c0 = w*8;
    #pragma unroll
    for (int pass = 0; pass < 2; ++pass) {
        int q = pass*28 + lane;             // float4 quad index within row
        bool act = (lane < 28);
        u64 acc[8][2];
        if (act) {
            #pragma unroll
            for (int j = 0; j < 8; ++j) {
                float bv = __ldg(b3 + c0 + j);
                acc[j][0] = pk2(bv, bv); acc[j][1] = acc[j][0];
            }
            #pragma unroll 4
            for (int ci = 0; ci < 64; ++ci) {
                ulonglong2 xv = *(const ulonglong2*)(xbuf + ci*224 + 4*q);
                const ulonglong2* wr = (const ulonglong2*)(w3ps + ci*64 + c0);
                ulonglong2 w01 = wr[0], w23 = wr[1], w45 = wr[2], w67 = wr[3];
                fma2(acc[0][0], w01.x, xv.x); fma2(acc[0][1], w01.x, xv.y);
                fma2(acc[1][0], w01.y, xv.x); fma2(acc[1][1], w01.y, xv.y);
                fma2(acc[2][0], w23.x, xv.x); fma2(acc[2][1], w23.x, xv.y);
                fma2(acc[3][0], w23.y, xv.x); fma2(acc[3][1], w23.y, xv.y);
                fma2(acc[4][0], w45.x, xv.x); fma2(acc[4][1], w45.x, xv.y);
                fma2(acc[5][0], w45.y, xv.x); fma2(acc[5][1], w45.y, xv.y);
                fma2(acc[6][0], w67.x, xv.x); fma2(acc[6][1], w67.x, xv.y);
                fma2(acc[7][0], w67.y, xv.x); fma2(acc[7][1], w67.y, xv.y);
            }
        }
        __syncthreads();                    // all reads of this range done
        if (act) {
            #pragma unroll
            for (int j = 0; j < 8; ++j) {
                u64* row = (u64*)(xbuf + (c0 + j)*224);
                row[2*q]     = acc[j][0];
                row[2*q + 1] = acc[j][1];
            }
        }
    }
    __syncthreads();    // x3 complete; w3ps dead -> ybuf alias live

    // ---- phase 3: out[c,t,u] = sum_v ysum[c,u,v]*x3[c,t,v] ----
    const float* ysrc = g_ysum + (size_t)n*OO*YSTR;
    float* myy = ybuf + w*YSTR;
    for (int cc = 0; cc < 8; ++cc) {
        int c = cc*8 + w;                   // this warp's channel
        // warp-private coalesced stage: 640 floats = 160 float4, 5/lane
        const float4* s4 = (const float4*)(ysrc + (size_t)c*YSTR);
        float4* d4 = (float4*)myy;
        #pragma unroll
        for (int j = 0; j < 5; ++j) d4[j*32 + lane] = s4[j*32 + lane];
        __syncwarp();
        if (lane < 25) {
            const float* yr = myy + lane*25;   // u = lane
            u64 yp[13];
            #pragma unroll
            for (int j = 0; j < 12; ++j) yp[j] = pk2(yr[2*j], yr[2*j+1]);
            yp[12] = pk2(yr[24], 0.0f);     // x3 pad holds b3, times 0 -> safe
            u64 acc2[8];
            #pragma unroll
            for (int t = 0; t < 8; ++t) acc2[t] = pk2(0.f, 0.f);
            const u64* xrow = (const u64*)(xbuf + c*224);
            #pragma unroll
            for (int j = 0; j < 13; ++j) {
                #pragma unroll
                for (int t = 0; t < 8; ++t)
                    fma2(acc2[t], yp[j], xrow[t*14 + j]);
            }
            float* od = out + (((size_t)n*64 + c)*128 + tt*8)*25 + lane;
            #pragma unroll
            for (int t = 0; t < 8; ++t) {
                float lo, hi; upk2(acc2[t], lo, hi);
                od[t*25] = lo + hi;
            }
        }
        __syncwarp();                       // reads done before next stage store
    }
}

// ============================================================
extern "C" void kernel_launch(void* const* d_in, const int* in_sizes, int n_in,
                              void* d_out, int out_size)
{
    (void)in_sizes; (void)n_in; (void)out_size;
    const float* x   = (const float*)d_in[0];
    const float* A   = (const float*)d_in[1];
    const float* w1  = (const float*)d_in[2];
    const float* b1  = (const float*)d_in[3];
    const float* g1  = (const float*)d_in[4];
    const float* be1 = (const float*)d_in[5];
    const float* w2  = (const float*)d_in[6];
    const float* b2  = (const float*)d_in[7];
    const float* g2  = (const float*)d_in[8];
    const float* be2 = (const float*)d_in[9];
    const float* w3  = (const float*)d_in[10];
    const float* b3  = (const float*)d_in[11];
    const float* w4  = (const float*)d_in[12];
    const float* b4  = (const float*)d_in[13];
    float* out = (float*)d_out;

    const int smemA = 512*8 + 12800*4 + 32*4;    // 55424
    const int smemC = 4096*8 + 64*224*4;         // 90112
    cudaFuncSetAttribute(kA, cudaFuncAttributeMaxDynamicSharedMemorySize, smemA);
    cudaFuncSetAttribute(kC, cudaFuncAttributeMaxDynamicSharedMemorySize, smemC);

    kA<<<dim3(4, 128), 256, smemA>>>(x, w1, b1, w2, b2);
    kB<<<128, 256>>>(A, g1, be1, g2, be2, w4, b4);
    kC<<<dim3(16, 128), 256, smemC>>>(x, w3, b3, out);
}